// round 4
// baseline (speedup 1.0000x reference)
#include <cuda_runtime.h>
#include <math.h>

#define HH 64
#define WW 64
#define BATCH 2
#define CCH 128
#define NPIX (BATCH*HH*WW)
#define KS 496   // 4 chunks * 124 (121 padded to 124 for float4 alignment)
#define GK 16    // GEMM K-chunk

// ---- scratch ----
__device__ float g_scores[(size_t)NPIX * KS];   // [pixel][cc*124+p]
__device__ float g_wperm[KS * CCH];             // [cc*124+p][o]
__device__ float g_m2[CCH * CCH];               // [c][o]
__device__ float g_m2p[4 * CCH * CCH];          // split-K partials

// ============================================================
// Prep A: permute W rows (s=4p+cc -> s'=cc*124+p), float4 vectorized.
// grid 62, block 256: 496 rows x 32 float4.
// ============================================================
__global__ __launch_bounds__(256) void prep_permute(const float* __restrict__ W) {
    int gid = blockIdx.x * 256 + threadIdx.x;     // 0..15871
    int row = gid >> 5, c4 = gid & 31;
    int cc = row / 124, p = row - cc * 124;
    float4 v = make_float4(0.f, 0.f, 0.f, 0.f);
    if (p < 121) v = ((const float4*)(W + (size_t)(4 * p + cc) * CCH))[c4];
    ((float4*)(g_wperm + (size_t)row * CCH))[c4] = v;
}

// ============================================================
// Prep B: M2 partials. grid (4 ksplit, 128 c), block 128 (o).
// partial[ks][c][o] = sum_{p in slice} pos[(s0+p)*32+cm] * W[(s0+p)*128+o]
// ============================================================
__global__ __launch_bounds__(128) void prep_m2_partial(const float* __restrict__ W,
                                                       const float* __restrict__ pos) {
    int o = threadIdx.x;
    int ks = blockIdx.x, c = blockIdx.y;
    int g = c >> 5, cm = c & 31;
    int s0 = 121 * g;
    int pbeg = ks * 31;
    int pend = (pbeg + 31 < 121) ? pbeg + 31 : 121;

    float a0 = 0.f, a1 = 0.f, a2 = 0.f, a3 = 0.f;
    int p = pbeg;
    for (; p + 4 <= pend; p += 4) {
        a0 += pos[(s0 + p + 0) * 32 + cm] * W[(size_t)(s0 + p + 0) * CCH + o];
        a1 += pos[(s0 + p + 1) * 32 + cm] * W[(size_t)(s0 + p + 1) * CCH + o];
        a2 += pos[(s0 + p + 2) * 32 + cm] * W[(size_t)(s0 + p + 2) * CCH + o];
        a3 += pos[(s0 + p + 3) * 32 + cm] * W[(size_t)(s0 + p + 3) * CCH + o];
    }
    for (; p < pend; p++)
        a0 += pos[(s0 + p) * 32 + cm] * W[(size_t)(s0 + p) * CCH + o];
    g_m2p[((size_t)ks * CCH + c) * CCH + o] = (a0 + a1) + (a2 + a3);
}

// grid 64, block 256
__global__ __launch_bounds__(256) void prep_m2_combine() {
    int i = blockIdx.x * 256 + threadIdx.x;       // 0..16383
    g_m2[i] = ((g_m2p[i] + g_m2p[16384 + i]) + (g_m2p[32768 + i] + g_m2p[49152 + i]));
}

// ============================================================
// Kernel 1: scores. 4x4 pixel tile per CTA, halo (14x14) per 32-ch
// chunk in smem (stride 36 floats). Thread = (pixel, lane); lane owns
// 16 consecutive p values => s-window 64 wide => at most 2 q chunks.
// ============================================================
__global__ __launch_bounds__(128) void score_kernel(const float* __restrict__ q,
                                                    const float* __restrict__ kv) {
    __shared__ float s_kv[196 * 36];
    __shared__ float s_q[16 * CCH];

    int tid = threadIdx.x;
    int b = blockIdx.z, h0 = blockIdx.y * 4, w0 = blockIdx.x * 4;

    for (int idx = tid; idx < 512; idx += 128) {
        int pix = idx >> 5, d4 = idx & 31;
        int ph = pix >> 2, pw = pix & 3;
        const float4* src = (const float4*)(q + (size_t)((b * HH + h0 + ph) * WW + (w0 + pw)) * CCH);
        ((float4*)s_q)[pix * 32 + d4] = src[d4];
    }
    __syncthreads();

    int pix = tid >> 3, lane = tid & 7;
    int ph = pix >> 2, pw = pix & 3;
    int pixg = (b * HH + h0 + ph) * WW + (w0 + pw);

    int s_lo = 64 * lane, s_hi = 64 * lane + 63;
    int g_lo = (s_lo >= 121) + (s_lo >= 242) + (s_lo >= 363);
    int g_hi = (s_hi >= 121) + (s_hi >= 242) + (s_hi >= 363);
    int thr = 121 * (g_lo + 1);      // s < thr  <=>  g(s) == g_lo (window spans <=1 boundary)

    float4 qA[8], qB[8];
    {
        const float4* sq4 = (const float4*)(s_q + pix * CCH);
        #pragma unroll
        for (int d4 = 0; d4 < 8; d4++) {
            qA[d4] = sq4[g_lo * 8 + d4];
            qB[d4] = sq4[g_hi * 8 + d4];
        }
    }

    // precompute smem position bases for this thread's 16 p values (reused for all 4 cc)
    int baseo[16];
    #pragma unroll
    for (int u = 0; u < 16; u++) {
        int p = lane * 16 + u;
        int pc = (p < 121) ? p : 120;
        int i = pc / 11;
        int j = pc - i * 11;
        baseo[u] = ((ph + i) * 14 + (pw + j)) * 9;
    }

    int npi = (lane == 7) ? 12 : 16;

    for (int cc = 0; cc < 4; cc++) {
        __syncthreads();
        for (int idx = tid; idx < 1568; idx += 128) {
            int pos = idx >> 3, d4 = idx & 7;
            int r = pos / 14, cpos = pos - r * 14;
            int y = h0 - 5 + r, x = w0 - 5 + cpos;
            float4 v = make_float4(0.f, 0.f, 0.f, 0.f);
            if ((unsigned)y < HH && (unsigned)x < WW)
                v = ((const float4*)(kv + (size_t)((b * HH + y) * WW + x) * CCH + cc * 32))[d4];
            *(float4*)&s_kv[pos * 36 + d4 * 4] = v;
        }
        __syncthreads();

        const float4* kv4 = (const float4*)s_kv;
        float* outp = g_scores + (size_t)pixg * KS + cc * 124 + lane * 16;
        #pragma unroll
        for (int pi0 = 0; pi0 < 16; pi0 += 4) {
            if (pi0 >= npi) break;
            float o4[4];
            #pragma unroll
            for (int u = 0; u < 4; u++) {
                int p = lane * 16 + pi0 + u;
                float acc = 0.f;
                if (p < 121) {
                    int base = baseo[pi0 + u];
                    if (4 * p + cc < thr) {
                        #pragma unroll
                        for (int d4 = 0; d4 < 8; d4++) {
                            float4 kvv = kv4[base + d4];
                            acc += kvv.x * qA[d4].x + kvv.y * qA[d4].y
                                 + kvv.z * qA[d4].z + kvv.w * qA[d4].w;
                        }
                    } else {
                        #pragma unroll
                        for (int d4 = 0; d4 < 8; d4++) {
                            float4 kvv = kv4[base + d4];
                            acc += kvv.x * qB[d4].x + kvv.y * qB[d4].y
                                 + kvv.z * qB[d4].z + kvv.w * qB[d4].w;
                        }
                    }
                }
                o4[u] = acc;
            }
            *(float4*)(outp + pi0) = make_float4(o4[0], o4[1], o4[2], o4[3]);
        }
    }
}

// ============================================================
// Kernel 2: fused GEMM + bias + gelu + residual + LN.
// 256 threads, tile 64M x 128N, thread tile 4M x 8N, K-chunk 16,
// double-buffered smem (one barrier per chunk), f32x2 FMA.
// ============================================================
__device__ __forceinline__ unsigned long long pk2(float x, float y) {
    unsigned long long r;
    asm("mov.b64 %0, {%1,%2};" : "=l"(r) : "f"(x), "f"(y));
    return r;
}
__device__ __forceinline__ void fma2(unsigned long long& d, unsigned long long a, unsigned long long b) {
    asm("fma.rn.f32x2 %0, %1, %2, %3;" : "=l"(d) : "l"(a), "l"(b), "l"(d));
}
__device__ __forceinline__ void upk2(unsigned long long v, float& x, float& y) {
    asm("mov.b64 {%0,%1}, %2;" : "=f"(x), "=f"(y) : "l"(v));
}

__global__ __launch_bounds__(256) void fused_gemm_kernel(
    const float* __restrict__ q,
    const float* __restrict__ bias,
    const float* __restrict__ lng,
    const float* __restrict__ lnb,
    float* __restrict__ out) {
    __shared__ float As[2][GK][64];     // 8KB
    __shared__ float Bs[2][GK][CCH];    // 16KB

    int tid = threadIdx.x;
    int tx = tid & 15, ty = tid >> 4;       // tx: N, ty: M
    int m0 = blockIdx.x * 64;

    int am = tid >> 2, ak4 = (tid & 3) * 4; // A-load: row, k-quad
    int bk = ty, bn = tx * 8;               // B-load: k-row, n-col

    unsigned long long acc[4][4];
    #pragma unroll
    for (int m = 0; m < 4; m++)
        #pragma unroll
        for (int n = 0; n < 4; n++) acc[m][n] = 0ULL;

    #pragma unroll 1
    for (int phase = 0; phase < 2; phase++) {
        const float* A  = (phase == 0) ? (g_scores + (size_t)m0 * KS) : (q + (size_t)m0 * CCH);
        int lda         = (phase == 0) ? KS : CCH;
        const float* Bm = (phase == 0) ? g_wperm : g_m2;
        int nk          = (phase == 0) ? (KS / GK) : (CCH / GK);

        float4 av  = *(const float4*)&A[(size_t)am * lda + ak4];
        float4 bv0 = *(const float4*)&Bm[(size_t)bk * CCH + bn];
        float4 bv1 = *(const float4*)&Bm[(size_t)bk * CCH + bn + 4];

        int buf = 0;
        As[0][ak4 + 0][am] = av.x;
        As[0][ak4 + 1][am] = av.y;
        As[0][ak4 + 2][am] = av.z;
        As[0][ak4 + 3][am] = av.w;
        *(float4*)&Bs[0][bk][bn]     = bv0;
        *(float4*)&Bs[0][bk][bn + 4] = bv1;
        __syncthreads();

        for (int kc = 0; kc < nk; kc++) {
            bool more = (kc + 1 < nk);
            if (more) {
                int kn = (kc + 1) * GK;
                av  = *(const float4*)&A[(size_t)am * lda + kn + ak4];
                bv0 = *(const float4*)&Bm[(size_t)(kn + bk) * CCH + bn];
                bv1 = *(const float4*)&Bm[(size_t)(kn + bk) * CCH + bn + 4];
            }
            const float* Asb = &As[buf][0][0];
            const float* Bsb = &Bs[buf][0][0];
            #pragma unroll
            for (int k = 0; k < GK; k++) {
                float4 a  = *(const float4*)&Asb[k * 64 + ty * 4];
                float4 b0 = *(const float4*)&Bsb[k * CCH + tx * 8];
                float4 b1 = *(const float4*)&Bsb[k * CCH + tx * 8 + 4];
                unsigned long long bp[4];
                bp[0] = pk2(b0.x, b0.y); bp[1] = pk2(b0.z, b0.w);
                bp[2] = pk2(b1.x, b1.y); bp[3] = pk2(b1.z, b1.w);
                float am4[4] = {a.x, a.y, a.z, a.w};
                #pragma unroll
                for (int m = 0; m < 4; m++) {
                    unsigned long long ad = pk2(am4[m], am4[m]);
                    #pragma unroll
                    for (int n = 0; n < 4; n++) fma2(acc[m][n], ad, bp[n]);
                }
            }
            if (more) {
                int nb = buf ^ 1;
                As[nb][ak4 + 0][am] = av.x;
                As[nb][ak4 + 1][am] = av.y;
                As[nb][ak4 + 2][am] = av.z;
                As[nb][ak4 + 3][am] = av.w;
                *(float4*)&Bs[nb][bk][bn]     = bv0;
                *(float4*)&Bs[nb][bk][bn + 4] = bv1;
                __syncthreads();
                buf = nb;
            }
        }
        __syncthreads();   // protect smem reuse across phases
    }

    // ---- epilogue: bias + gelu(exact erf) + residual + layernorm ----
    float bi[8], gg[8], bb[8];
    {
        float4 t0 = *(const float4*)&bias[tx * 8];
        float4 t1 = *(const float4*)&bias[tx * 8 + 4];
        bi[0] = t0.x; bi[1] = t0.y; bi[2] = t0.z; bi[3] = t0.w;
        bi[4] = t1.x; bi[5] = t1.y; bi[6] = t1.z; bi[7] = t1.w;
        t0 = *(const float4*)&lng[tx * 8]; t1 = *(const float4*)&lng[tx * 8 + 4];
        gg[0] = t0.x; gg[1] = t0.y; gg[2] = t0.z; gg[3] = t0.w;
        gg[4] = t1.x; gg[5] = t1.y; gg[6] = t1.z; gg[7] = t1.w;
        t0 = *(const float4*)&lnb[tx * 8]; t1 = *(const float4*)&lnb[tx * 8 + 4];
        bb[0] = t0.x; bb[1] = t0.y; bb[2] = t0.z; bb[3] = t0.w;
        bb[4] = t1.x; bb[5] = t1.y; bb[6] = t1.z; bb[7] = t1.w;
    }
    const float inv128 = 1.0f / 128.0f;
    const float rsqrt2 = 0.70710678118654752f;

    #pragma unroll
    for (int mm = 0; mm < 4; mm++) {
        int pixg = m0 + ty * 4 + mm;
        float4 q0 = *(const float4*)&q[(size_t)pixg * CCH + tx * 8];
        float4 q1 = *(const float4*)&q[(size_t)pixg * CCH + tx * 8 + 4];
        float qv[8] = {q0.x, q0.y, q0.z, q0.w, q1.x, q1.y, q1.z, q1.w};
        float x[8];
        float s1 = 0.f, s2 = 0.f;
        #pragma unroll
        for (int n2 = 0; n2 < 4; n2++) {
            float lo, hi;
            upk2(acc[mm][n2], lo, hi);
            float p0 = lo + bi[n2 * 2 + 0];
            float p1 = hi + bi[n2 * 2 + 1];
            float e0 = 0.5f * p0 * (1.f + erff(p0 * rsqrt2));
            float e1 = 0.5f * p1 * (1.f + erff(p1 * rsqrt2));
            float x0 = e0 + qv[n2 * 2 + 0];
            float x1 = e1 + qv[n2 * 2 + 1];
            x[n2 * 2 + 0] = x0; x[n2 * 2 + 1] = x1;
            s1 += x0 + x1;
            s2 += x0 * x0 + x1 * x1;
        }
        // lane = (ty&1)*16 + tx, so xor over {1,2,4,8} reduces across tx only
        #pragma unroll
        for (int ofs = 8; ofs >= 1; ofs >>= 1) {
            s1 += __shfl_xor_sync(0xffffffffu, s1, ofs);
            s2 += __shfl_xor_sync(0xffffffffu, s2, ofs);
        }
        float mean = s1 * inv128;
        float var = s2 * inv128 - mean * mean;
        float rstd = rsqrtf(var + 1e-5f);
        float o[8];
        #pragma unroll
        for (int n = 0; n < 8; n++)
            o[n] = (x[n] - mean) * rstd * gg[n] + bb[n];
        *(float4*)&out[(size_t)pixg * CCH + tx * 8] = make_float4(o[0], o[1], o[2], o[3]);
        *(float4*)&out[(size_t)pixg * CCH + tx * 8 + 4] = make_float4(o[4], o[5], o[6], o[7]);
    }
}

// ============================================================
extern "C" void kernel_launch(void* const* d_in, const int* in_sizes, int n_in,
                              void* d_out, int out_size) {
    const float* q    = (const float*)d_in[0];
    const float* kv   = (const float*)d_in[1];
    const float* pos  = (const float*)d_in[2];
    const float* W    = (const float*)d_in[3];
    const float* bias = (const float*)d_in[4];
    const float* lng  = (const float*)d_in[5];
    const float* lnb  = (const float*)d_in[6];
    float* out = (float*)d_out;

    prep_permute<<<62, 256>>>(W);
    prep_m2_partial<<<dim3(4, CCH), 128>>>(W, pos);
    prep_m2_combine<<<64, 256>>>();
    score_kernel<<<dim3(WW / 4, HH / 4, BATCH), 128>>>(q, kv);
    fused_gemm_kernel<<<NPIX / 64, 256>>>(q, bias, lng, lnb, out);
}

// round 7
// speedup vs baseline: 1.2098x; 1.2098x over previous
#include <cuda_runtime.h>
#include <math.h>

#define HH 64
#define WW 64
#define BATCH 2
#define CCH 128
#define NPIX (BATCH*HH*WW)
#define KS 496   // 4 chunks * 124 (121 padded to 124)

// ---- scratch ----
__device__ float g_scores[(size_t)NPIX * KS];   // [pixel][cc*124+p]
__device__ float g_wperm[KS * CCH];             // [cc*124+p][o]
__device__ float g_m2[CCH * CCH];               // [c][o]
__device__ float g_m2p[4 * CCH * CCH];          // split-K partials

// ============================================================
// Prep A: permute W rows (s=4p+cc -> s'=cc*124+p), float4 vectorized.
// ============================================================
__global__ __launch_bounds__(256) void prep_permute(const float* __restrict__ W) {
    int gid = blockIdx.x * 256 + threadIdx.x;     // 0..15871
    int row = gid >> 5, c4 = gid & 31;
    int cc = row / 124, p = row - cc * 124;
    float4 v = make_float4(0.f, 0.f, 0.f, 0.f);
    if (p < 121) v = ((const float4*)(W + (size_t)(4 * p + cc) * CCH))[c4];
    ((float4*)(g_wperm + (size_t)row * CCH))[c4] = v;
}

// ============================================================
// Prep B: M2 partials + combine (split-K, deterministic)
// ============================================================
__global__ __launch_bounds__(128) void prep_m2_partial(const float* __restrict__ W,
                                                       const float* __restrict__ pos) {
    int o = threadIdx.x;
    int ks = blockIdx.x, c = blockIdx.y;
    int g = c >> 5, cm = c & 31;
    int s0 = 121 * g;
    int pbeg = ks * 31;
    int pend = (pbeg + 31 < 121) ? pbeg + 31 : 121;

    float a0 = 0.f, a1 = 0.f, a2 = 0.f, a3 = 0.f;
    int p = pbeg;
    for (; p + 4 <= pend; p += 4) {
        a0 += pos[(s0 + p + 0) * 32 + cm] * W[(size_t)(s0 + p + 0) * CCH + o];
        a1 += pos[(s0 + p + 1) * 32 + cm] * W[(size_t)(s0 + p + 1) * CCH + o];
        a2 += pos[(s0 + p + 2) * 32 + cm] * W[(size_t)(s0 + p + 2) * CCH + o];
        a3 += pos[(s0 + p + 3) * 32 + cm] * W[(size_t)(s0 + p + 3) * CCH + o];
    }
    for (; p < pend; p++)
        a0 += pos[(s0 + p) * 32 + cm] * W[(size_t)(s0 + p) * CCH + o];
    g_m2p[((size_t)ks * CCH + c) * CCH + o] = (a0 + a1) + (a2 + a3);
}

__global__ __launch_bounds__(256) void prep_m2_combine() {
    int i = blockIdx.x * 256 + threadIdx.x;
    g_m2[i] = ((g_m2p[i] + g_m2p[16384 + i]) + (g_m2p[32768 + i] + g_m2p[49152 + i]));
}

// ============================================================
// Kernel 1 v2: scores with register-window kv reuse.
// CTA: 8x8 pixel tile, 256 threads = 16 quads x 4 cc x 4 dgroups.
// Thread owns 4 adjacent pixels (one row), chunk cc, d4 in {dg, dg+4}.
// For each row-offset i: 14-wide float4 window serves 4px x 11j.
// Reduce over 4 dg lanes via shfl_xor(1),(2); dg==0 stores.
// smem: s_kv[cc][324 pos][36f]  (cc stride 2916 f4 == 4 mod 8 -> CF loads)
//       s_q [64 px][132f]
// ============================================================
#define KV_CC_STRIDE 11664           // 324*36 floats
#define SMEM_SCORE ((4*KV_CC_STRIDE + 64*132) * 4)

__global__ __launch_bounds__(256, 1) void score_kernel(const float* __restrict__ q,
                                                       const float* __restrict__ kv) {
    extern __shared__ float smem[];
    float* s_kv = smem;
    float* s_q  = smem + 4 * KV_CC_STRIDE;

    const int tid = threadIdx.x;
    const int b = blockIdx.z, h0 = blockIdx.y * 8, w0 = blockIdx.x * 8;

    // ---- stage kv halo (18x18 x 128ch), conflict-free layout ----
    for (int idx = tid; idx < 324 * 32; idx += 256) {
        int pos = idx >> 5, c4 = idx & 31;
        int r = pos / 18, xc = pos - r * 18;
        int y = h0 - 5 + r, x = w0 - 5 + xc;
        float4 v = make_float4(0.f, 0.f, 0.f, 0.f);
        if ((unsigned)y < HH && (unsigned)x < WW)
            v = ((const float4*)(kv + (size_t)((b * HH + y) * WW + x) * CCH))[c4];
        int cc = c4 >> 3, d4 = c4 & 7;
        *(float4*)&s_kv[cc * KV_CC_STRIDE + pos * 36 + d4 * 4] = v;
    }
    // ---- stage q tile ----
    for (int idx = tid; idx < 64 * 32; idx += 256) {
        int px = idx >> 5, c4 = idx & 31;
        int ph = px >> 3, pw = px & 7;
        float4 v = ((const float4*)(q + (size_t)((b * HH + h0 + ph) * WW + (w0 + pw)) * CCH))[c4];
        *(float4*)&s_q[px * 132 + c4 * 4] = v;
    }
    __syncthreads();

    const int dg   = tid & 3;
    const int cc   = (tid >> 2) & 3;
    const int quad = tid >> 4;                  // 0..15
    const int qrow = quad >> 1, qcol = quad & 1;
    const int pxb  = qrow * 8 + qcol * 4;       // local pixel index of quad start
    const int pixg0 = (b * HH + h0 + qrow) * WW + (w0 + qcol * 4);
    const float* ccb = s_kv + cc * KV_CC_STRIDE;

    for (int i = 0; i < 11; i++) {
        float acc[4][11];
        #pragma unroll
        for (int k = 0; k < 4; k++)
            #pragma unroll
            for (int j = 0; j < 11; j++) acc[k][j] = 0.f;

        int sbase = 44 * i + cc;
        int gA = (sbase >= 363) ? 3 : (sbase >= 242) ? 2 : (sbase >= 121) ? 1 : 0;
        int gB = (gA < 3) ? gA + 1 : 3;
        int thr2 = 121 * (gA + 1);

        #pragma unroll
        for (int hd = 0; hd < 2; hd++) {
            int d4 = dg + 4 * hd;
            // q registers for this thread's 4 channels, both possible head chunks
            float4 qA[4], qB[4];
            #pragma unroll
            for (int k = 0; k < 4; k++) {
                qA[k] = *(const float4*)&s_q[(pxb + k) * 132 + gA * 32 + d4 * 4];
                qB[k] = *(const float4*)&s_q[(pxb + k) * 132 + gB * 32 + d4 * 4];
            }
            // 14-wide window over halo row (qrow+i), cols qcol*4 .. qcol*4+13
            float4 win[14];
            const float* rowp = ccb + ((qrow + i) * 18 + qcol * 4) * 36 + d4 * 4;
            #pragma unroll
            for (int x = 0; x < 14; x++) win[x] = *(const float4*)&rowp[x * 36];

            #pragma unroll
            for (int j = 0; j < 11; j++) {
                bool sel = (sbase + 4 * j) >= thr2;
                #pragma unroll
                for (int k = 0; k < 4; k++) {
                    float4 qv = sel ? qB[k] : qA[k];
                    float4 kvv = win[j + k];
                    acc[k][j] += kvv.x * qv.x + kvv.y * qv.y
                               + kvv.z * qv.z + kvv.w * qv.w;
                }
            }
        }

        // reduce across the 4 dg lanes; dg==0 writes
        #pragma unroll
        for (int k = 0; k < 4; k++) {
            float* outp = g_scores + (size_t)(pixg0 + k) * KS + cc * 124 + 11 * i;
            #pragma unroll
            for (int j = 0; j < 11; j++) {
                float v = acc[k][j];
                v += __shfl_xor_sync(0xffffffffu, v, 1);
                v += __shfl_xor_sync(0xffffffffu, v, 2);
                if (dg == 0) outp[j] = v;
            }
        }
    }
}

// ============================================================
// Kernel 2: fused GEMM + bias + gelu + residual + LN (R1 version — known good)
// ============================================================
__device__ __forceinline__ unsigned long long pk2(float x, float y) {
    unsigned long long r;
    asm("mov.b64 %0, {%1,%2};" : "=l"(r) : "f"(x), "f"(y));
    return r;
}
__device__ __forceinline__ void fma2(unsigned long long& d, unsigned long long a, unsigned long long b) {
    asm("fma.rn.f32x2 %0, %1, %2, %3;" : "=l"(d) : "l"(a), "l"(b), "l"(d));
}
__device__ __forceinline__ void upk2(unsigned long long v, float& x, float& y) {
    asm("mov.b64 {%0,%1}, %2;" : "=f"(x), "=f"(y) : "l"(v));
}

__global__ __launch_bounds__(128) void fused_gemm_kernel(
    const float* __restrict__ q,
    const float* __restrict__ bias,
    const float* __restrict__ lng,
    const float* __restrict__ lnb,
    float* __restrict__ out) {
    __shared__ float As[8 * 64];    // [k][m]
    __shared__ float Bs[8 * CCH];   // [k][n]

    int tid = threadIdx.x;
    int tx = tid & 15, ty = tid >> 4;
    int m0 = blockIdx.x * 64;

    unsigned long long acc[8][4];
    #pragma unroll
    for (int m = 0; m < 8; m++)
        #pragma unroll
        for (int n = 0; n < 4; n++) acc[m][n] = 0ULL;

    int pixL = tid >> 1, half = tid & 1;

    for (int phase = 0; phase < 2; phase++) {
        const float* A = (phase == 0) ? (g_scores + (size_t)m0 * KS) : (q + (size_t)m0 * CCH);
        int lda = (phase == 0) ? KS : CCH;
        const float* Bm = (phase == 0) ? g_wperm : g_m2;
        int nk = (phase == 0) ? (KS / 8) : (CCH / 8);

        float4 av = *(const float4*)&A[(size_t)pixL * lda + half * 4];
        float4 bv0 = *(const float4*)&Bm[(size_t)(tid >> 5) * CCH + (tid & 31) * 4];
        float4 bv1 = *(const float4*)&Bm[(size_t)(4 + (tid >> 5)) * CCH + (tid & 31) * 4];

        for (int kc = 0; kc < nk; kc++) {
            __syncthreads();
            As[(half * 4 + 0) * 64 + pixL] = av.x;
            As[(half * 4 + 1) * 64 + pixL] = av.y;
            As[(half * 4 + 2) * 64 + pixL] = av.z;
            As[(half * 4 + 3) * 64 + pixL] = av.w;
            *(float4*)&Bs[(tid >> 5) * CCH + (tid & 31) * 4] = bv0;
            *(float4*)&Bs[(4 + (tid >> 5)) * CCH + (tid & 31) * 4] = bv1;
            __syncthreads();
            if (kc + 1 < nk) {
                int kn = (kc + 1) * 8;
                av = *(const float4*)&A[(size_t)pixL * lda + kn + half * 4];
                bv0 = *(const float4*)&Bm[(size_t)(kn + (tid >> 5)) * CCH + (tid & 31) * 4];
                bv1 = *(const float4*)&Bm[(size_t)(kn + 4 + (tid >> 5)) * CCH + (tid & 31) * 4];
            }
            #pragma unroll
            for (int k = 0; k < 8; k++) {
                float4 a0 = *(const float4*)&As[k * 64 + ty * 8];
                float4 a1 = *(const float4*)&As[k * 64 + ty * 8 + 4];
                float4 b0 = *(const float4*)&Bs[k * CCH + tx * 8];
                float4 b1 = *(const float4*)&Bs[k * CCH + tx * 8 + 4];
                unsigned long long bp[4];
                bp[0] = pk2(b0.x, b0.y); bp[1] = pk2(b0.z, b0.w);
                bp[2] = pk2(b1.x, b1.y); bp[3] = pk2(b1.z, b1.w);
                float am[8] = {a0.x, a0.y, a0.z, a0.w, a1.x, a1.y, a1.z, a1.w};
                #pragma unroll
                for (int m = 0; m < 8; m++) {
                    unsigned long long ad = pk2(am[m], am[m]);
                    #pragma unroll
                    for (int n = 0; n < 4; n++) fma2(acc[m][n], ad, bp[n]);
                }
            }
        }
        __syncthreads();
    }

    // ---- epilogue: bias + gelu(exact erf) + residual + layernorm ----
    float bi[8], gg[8], bb[8];
    {
        float4 t0 = *(const float4*)&bias[tx * 8];
        float4 t1 = *(const float4*)&bias[tx * 8 + 4];
        bi[0] = t0.x; bi[1] = t0.y; bi[2] = t0.z; bi[3] = t0.w;
        bi[4] = t1.x; bi[5] = t1.y; bi[6] = t1.z; bi[7] = t1.w;
        t0 = *(const float4*)&lng[tx * 8]; t1 = *(const float4*)&lng[tx * 8 + 4];
        gg[0] = t0.x; gg[1] = t0.y; gg[2] = t0.z; gg[3] = t0.w;
        gg[4] = t1.x; gg[5] = t1.y; gg[6] = t1.z; gg[7] = t1.w;
        t0 = *(const float4*)&lnb[tx * 8]; t1 = *(const float4*)&lnb[tx * 8 + 4];
        bb[0] = t0.x; bb[1] = t0.y; bb[2] = t0.z; bb[3] = t0.w;
        bb[4] = t1.x; bb[5] = t1.y; bb[6] = t1.z; bb[7] = t1.w;
    }
    const float inv128 = 1.0f / 128.0f;
    const float rsqrt2 = 0.70710678118654752f;

    #pragma unroll
    for (int mm = 0; mm < 8; mm++) {
        int pixg = m0 + ty * 8 + mm;
        float4 q0 = *(const float4*)&q[(size_t)pixg * CCH + tx * 8];
        float4 q1 = *(const float4*)&q[(size_t)pixg * CCH + tx * 8 + 4];
        float qv[8] = {q0.x, q0.y, q0.z, q0.w, q1.x, q1.y, q1.z, q1.w};
        float x[8];
        float s1 = 0.f, s2 = 0.f;
        #pragma unroll
        for (int n2 = 0; n2 < 4; n2++) {
            float lo, hi;
            upk2(acc[mm][n2], lo, hi);
            float p0 = lo + bi[n2 * 2 + 0];
            float p1 = hi + bi[n2 * 2 + 1];
            float e0 = 0.5f * p0 * (1.f + erff(p0 * rsqrt2));
            float e1 = 0.5f * p1 * (1.f + erff(p1 * rsqrt2));
            float x0 = e0 + qv[n2 * 2 + 0];
            float x1 = e1 + qv[n2 * 2 + 1];
            x[n2 * 2 + 0] = x0; x[n2 * 2 + 1] = x1;
            s1 += x0 + x1;
            s2 += x0 * x0 + x1 * x1;
        }
        #pragma unroll
        for (int ofs = 8; ofs >= 1; ofs >>= 1) {
            s1 += __shfl_xor_sync(0xffffffffu, s1, ofs);
            s2 += __shfl_xor_sync(0xffffffffu, s2, ofs);
        }
        float mean = s1 * inv128;
        float var = s2 * inv128 - mean * mean;
        float rstd = rsqrtf(var + 1e-5f);
        float o[8];
        #pragma unroll
        for (int n = 0; n < 8; n++)
            o[n] = (x[n] - mean) * rstd * gg[n] + bb[n];
        *(float4*)&out[(size_t)pixg * CCH + tx * 8] = make_float4(o[0], o[1], o[2], o[3]);
        *(float4*)&out[(size_t)pixg * CCH + tx * 8 + 4] = make_float4(o[4], o[5], o[6], o[7]);
    }
}

// ============================================================
extern "C" void kernel_launch(void* const* d_in, const int* in_sizes, int n_in,
                              void* d_out, int out_size) {
    const float* q    = (const float*)d_in[0];
    const float* kv   = (const float*)d_in[1];
    const float* pos  = (const float*)d_in[2];
    const float* W    = (const float*)d_in[3];
    const float* bias = (const float*)d_in[4];
    const float* lng  = (const float*)d_in[5];
    const float* lnb  = (const float*)d_in[6];
    float* out = (float*)d_out;

    static int smem_set = 0;
    if (!smem_set) {
        cudaFuncSetAttribute(score_kernel,
                             cudaFuncAttributeMaxDynamicSharedMemorySize, SMEM_SCORE);
        smem_set = 1;
    }

    prep_permute<<<62, 256>>>(W);
    prep_m2_partial<<<dim3(4, CCH), 128>>>(W, pos);
    prep_m2_combine<<<64, 256>>>();
    score_kernel<<<dim3(WW / 8, HH / 8, BATCH), 256, SMEM_SCORE>>>(q, kv);
    fused_gemm_kernel<<<NPIX / 64, 128>>>(q, bias, lng, lnb, out);
}

// round 8
// speedup vs baseline: 1.5671x; 1.2953x over previous
#include <cuda_runtime.h>
#include <math.h>

#define HH 64
#define WW 64
#define BATCH 2
#define CCH 128
#define NPIX (BATCH*HH*WW)
#define KS 496   // 4 chunks * 124 (121 padded to 124)

// ---- scratch ----
__device__ float g_scores[(size_t)NPIX * KS];   // [pixel][cc*124+p]
__device__ float g_wperm[KS * CCH];             // [cc*124+p][o]
__device__ float g_m2[CCH * CCH];               // [c][o]
__device__ float g_m2p[4 * CCH * CCH];          // split-K partials

// ============================================================
// Prep A: permute W rows (s=4p+cc -> s'=cc*124+p), float4 vectorized.
// ============================================================
__global__ __launch_bounds__(256) void prep_permute(const float* __restrict__ W) {
    int gid = blockIdx.x * 256 + threadIdx.x;     // 0..15871
    int row = gid >> 5, c4 = gid & 31;
    int cc = row / 124, p = row - cc * 124;
    float4 v = make_float4(0.f, 0.f, 0.f, 0.f);
    if (p < 121) v = ((const float4*)(W + (size_t)(4 * p + cc) * CCH))[c4];
    ((float4*)(g_wperm + (size_t)row * CCH))[c4] = v;
}

// ============================================================
// Prep B: M2 partials + combine (split-K, deterministic)
// ============================================================
__global__ __launch_bounds__(128) void prep_m2_partial(const float* __restrict__ W,
                                                       const float* __restrict__ pos) {
    int o = threadIdx.x;
    int ks = blockIdx.x, c = blockIdx.y;
    int g = c >> 5, cm = c & 31;
    int s0 = 121 * g;
    int pbeg = ks * 31;
    int pend = (pbeg + 31 < 121) ? pbeg + 31 : 121;

    float a0 = 0.f, a1 = 0.f, a2 = 0.f, a3 = 0.f;
    int p = pbeg;
    for (; p + 4 <= pend; p += 4) {
        a0 += pos[(s0 + p + 0) * 32 + cm] * W[(size_t)(s0 + p + 0) * CCH + o];
        a1 += pos[(s0 + p + 1) * 32 + cm] * W[(size_t)(s0 + p + 1) * CCH + o];
        a2 += pos[(s0 + p + 2) * 32 + cm] * W[(size_t)(s0 + p + 2) * CCH + o];
        a3 += pos[(s0 + p + 3) * 32 + cm] * W[(size_t)(s0 + p + 3) * CCH + o];
    }
    for (; p < pend; p++)
        a0 += pos[(s0 + p) * 32 + cm] * W[(size_t)(s0 + p) * CCH + o];
    g_m2p[((size_t)ks * CCH + c) * CCH + o] = (a0 + a1) + (a2 + a3);
}

__global__ __launch_bounds__(256) void prep_m2_combine() {
    int i = blockIdx.x * 256 + threadIdx.x;
    g_m2[i] = ((g_m2p[i] + g_m2p[16384 + i]) + (g_m2p[32768 + i] + g_m2p[49152 + i]));
}

// ============================================================
// Kernel 1 v3: scores with register-window kv reuse.
// CTA: 8x8 pixel tile, 256 threads = 16 quads x 4 cc x 4 dgroups.
// Fixes vs v2: hd loop NOT unrolled (regs ~150, no spill);
// head-boundary crossing only at i in {2,5,8} -> SEL-free fast path.
// ============================================================
#define KV_CC_STRIDE 11664           // 324*36 floats
#define SMEM_SCORE ((4*KV_CC_STRIDE + 64*132) * 4)

__global__ __launch_bounds__(256, 1) void score_kernel(const float* __restrict__ q,
                                                       const float* __restrict__ kv) {
    extern __shared__ float smem[];
    float* s_kv = smem;
    float* s_q  = smem + 4 * KV_CC_STRIDE;

    const int tid = threadIdx.x;
    const int b = blockIdx.z, h0 = blockIdx.y * 8, w0 = blockIdx.x * 8;

    // ---- stage kv halo (18x18 x 128ch), conflict-free layout ----
    for (int idx = tid; idx < 324 * 32; idx += 256) {
        int pos = idx >> 5, c4 = idx & 31;
        int r = pos / 18, xc = pos - r * 18;
        int y = h0 - 5 + r, x = w0 - 5 + xc;
        float4 v = make_float4(0.f, 0.f, 0.f, 0.f);
        if ((unsigned)y < HH && (unsigned)x < WW)
            v = ((const float4*)(kv + (size_t)((b * HH + y) * WW + x) * CCH))[c4];
        int cc = c4 >> 3, d4 = c4 & 7;
        *(float4*)&s_kv[cc * KV_CC_STRIDE + pos * 36 + d4 * 4] = v;
    }
    // ---- stage q tile ----
    for (int idx = tid; idx < 64 * 32; idx += 256) {
        int px = idx >> 5, c4 = idx & 31;
        int ph = px >> 3, pw = px & 7;
        float4 v = ((const float4*)(q + (size_t)((b * HH + h0 + ph) * WW + (w0 + pw)) * CCH))[c4];
        *(float4*)&s_q[px * 132 + c4 * 4] = v;
    }
    __syncthreads();

    const int dg   = tid & 3;
    const int cc   = (tid >> 2) & 3;
    const int quad = tid >> 4;                  // 0..15
    const int qrow = quad >> 1, qcol = quad & 1;
    const int pxb  = qrow * 8 + qcol * 4;
    const int pixg0 = (b * HH + h0 + qrow) * WW + (w0 + qcol * 4);
    const float* ccb = s_kv + cc * KV_CC_STRIDE;

    #pragma unroll 1
    for (int i = 0; i < 11; i++) {
        float acc[4][11];
        #pragma unroll
        for (int k = 0; k < 4; k++)
            #pragma unroll
            for (int j = 0; j < 11; j++) acc[k][j] = 0.f;

        // head chunk: range [44i, 44i+43] crosses a 121-boundary only at i=2,5,8
        int gA = (44 * i) / 121;
        bool cross = (i == 2) | (i == 5) | (i == 8);
        int sbase = 44 * i + cc;
        int thr2 = 121 * (gA + 1);

        #pragma unroll 1
        for (int hd = 0; hd < 2; hd++) {
            int d4 = dg + 4 * hd;
            float4 qA[4];
            #pragma unroll
            for (int k = 0; k < 4; k++)
                qA[k] = *(const float4*)&s_q[(pxb + k) * 132 + gA * 32 + d4 * 4];
            float4 win[14];
            const float* rowp = ccb + ((qrow + i) * 18 + qcol * 4) * 36 + d4 * 4;
            #pragma unroll
            for (int x = 0; x < 14; x++) win[x] = *(const float4*)&rowp[x * 36];

            if (!cross) {
                #pragma unroll
                for (int j = 0; j < 11; j++) {
                    #pragma unroll
                    for (int k = 0; k < 4; k++) {
                        float4 kvv = win[j + k];
                        acc[k][j] += kvv.x * qA[k].x + kvv.y * qA[k].y
                                   + kvv.z * qA[k].z + kvv.w * qA[k].w;
                    }
                }
            } else {
                float4 qB[4];
                #pragma unroll
                for (int k = 0; k < 4; k++)
                    qB[k] = *(const float4*)&s_q[(pxb + k) * 132 + (gA + 1) * 32 + d4 * 4];
                #pragma unroll
                for (int j = 0; j < 11; j++) {
                    bool sel = (sbase + 4 * j) >= thr2;
                    #pragma unroll
                    for (int k = 0; k < 4; k++) {
                        float4 qv = sel ? qB[k] : qA[k];
                        float4 kvv = win[j + k];
                        acc[k][j] += kvv.x * qv.x + kvv.y * qv.y
                                   + kvv.z * qv.z + kvv.w * qv.w;
                    }
                }
            }
        }

        // reduce across the 4 dg lanes; dg==0 writes
        #pragma unroll
        for (int k = 0; k < 4; k++) {
            float* outp = g_scores + (size_t)(pixg0 + k) * KS + cc * 124 + 11 * i;
            #pragma unroll
            for (int j = 0; j < 11; j++) {
                float v = acc[k][j];
                v += __shfl_xor_sync(0xffffffffu, v, 1);
                v += __shfl_xor_sync(0xffffffffu, v, 2);
                if (dg == 0) outp[j] = v;
            }
        }
    }
}

// ============================================================
// Kernel 2 v3: fused GEMM + bias + gelu + residual + LN.
// 128 threads, 64M x 128N, 8x8 thread tile. Double-buffered smem
// (1 barrier/chunk). Thread N cols split tx*4 and 64+tx*4 so the
// B LDS.128 loads are bank-conflict-free; B loaded as ulonglong2
// (pre-packed f32x2 operands, no pack movs).
// ============================================================
typedef unsigned long long ull;
__device__ __forceinline__ ull pk2(float x, float y) {
    ull r;
    asm("mov.b64 %0, {%1,%2};" : "=l"(r) : "f"(x), "f"(y));
    return r;
}
__device__ __forceinline__ void fma2(ull& d, ull a, ull b) {
    asm("fma.rn.f32x2 %0, %1, %2, %3;" : "=l"(d) : "l"(a), "l"(b), "l"(d));
}
__device__ __forceinline__ void upk2(ull v, float& x, float& y) {
    asm("mov.b64 {%0,%1}, %2;" : "=f"(x), "=f"(y) : "l"(v));
}

__global__ __launch_bounds__(128) void fused_gemm_kernel(
    const float* __restrict__ q,
    const float* __restrict__ bias,
    const float* __restrict__ lng,
    const float* __restrict__ lnb,
    float* __restrict__ out) {
    __shared__ __align__(16) float As[2][8][64];
    __shared__ __align__(16) float Bs[2][8][CCH];

    int tid = threadIdx.x;
    int tx = tid & 15, ty = tid >> 4;
    int m0 = blockIdx.x * 64;
    int n0 = tx * 4, n1 = 64 + tx * 4;     // split N columns (CF smem loads)

    ull acc[8][4];
    #pragma unroll
    for (int m = 0; m < 8; m++)
        #pragma unroll
        for (int n = 0; n < 4; n++) acc[m][n] = 0ULL;

    int pixL = tid >> 1, half = tid & 1;
    int brow = tid >> 5, bcol = (tid & 31) * 4;

    #pragma unroll 1
    for (int phase = 0; phase < 2; phase++) {
        const float* A = (phase == 0) ? (g_scores + (size_t)m0 * KS) : (q + (size_t)m0 * CCH);
        int lda = (phase == 0) ? KS : CCH;
        const float* Bm = (phase == 0) ? g_wperm : g_m2;
        int nk = (phase == 0) ? (KS / 8) : (CCH / 8);

        float4 av  = *(const float4*)&A[(size_t)pixL * lda + half * 4];
        float4 bv0 = *(const float4*)&Bm[(size_t)brow * CCH + bcol];
        float4 bv1 = *(const float4*)&Bm[(size_t)(brow + 4) * CCH + bcol];

        int buf = 0;
        As[0][half * 4 + 0][pixL] = av.x;
        As[0][half * 4 + 1][pixL] = av.y;
        As[0][half * 4 + 2][pixL] = av.z;
        As[0][half * 4 + 3][pixL] = av.w;
        *(float4*)&Bs[0][brow][bcol]     = bv0;
        *(float4*)&Bs[0][brow + 4][bcol] = bv1;
        __syncthreads();

        for (int kc = 0; kc < nk; kc++) {
            bool more = (kc + 1 < nk);
            if (more) {
                int kn = (kc + 1) * 8;
                av  = *(const float4*)&A[(size_t)pixL * lda + kn + half * 4];
                bv0 = *(const float4*)&Bm[(size_t)(kn + brow) * CCH + bcol];
                bv1 = *(const float4*)&Bm[(size_t)(kn + brow + 4) * CCH + bcol];
            }
            #pragma unroll
            for (int k = 0; k < 8; k++) {
                float4 a0 = *(const float4*)&As[buf][k][ty * 8];
                float4 a1 = *(const float4*)&As[buf][k][ty * 8 + 4];
                ulonglong2 bq0 = *(const ulonglong2*)&Bs[buf][k][n0];
                ulonglong2 bq1 = *(const ulonglong2*)&Bs[buf][k][n1];
                ull bp[4] = {bq0.x, bq0.y, bq1.x, bq1.y};
                float am[8] = {a0.x, a0.y, a0.z, a0.w, a1.x, a1.y, a1.z, a1.w};
                #pragma unroll
                for (int m = 0; m < 8; m++) {
                    ull ad = pk2(am[m], am[m]);
                    #pragma unroll
                    for (int n = 0; n < 4; n++) fma2(acc[m][n], ad, bp[n]);
                }
            }
            if (more) {
                int nb = buf ^ 1;
                As[nb][half * 4 + 0][pixL] = av.x;
                As[nb][half * 4 + 1][pixL] = av.y;
                As[nb][half * 4 + 2][pixL] = av.z;
                As[nb][half * 4 + 3][pixL] = av.w;
                *(float4*)&Bs[nb][brow][bcol]     = bv0;
                *(float4*)&Bs[nb][brow + 4][bcol] = bv1;
                __syncthreads();
                buf = nb;
            }
        }
        __syncthreads();   // smem reuse across phases
    }

    // ---- epilogue: bias + gelu(exact erf) + residual + layernorm ----
    // thread covers cols [n0..n0+3] (acc n=0,1) and [n1..n1+3] (acc n=2,3)
    float bi[8], gg[8], bb[8];
    {
        float4 t0 = *(const float4*)&bias[n0];
        float4 t1 = *(const float4*)&bias[n1];
        bi[0] = t0.x; bi[1] = t0.y; bi[2] = t0.z; bi[3] = t0.w;
        bi[4] = t1.x; bi[5] = t1.y; bi[6] = t1.z; bi[7] = t1.w;
        t0 = *(const float4*)&lng[n0]; t1 = *(const float4*)&lng[n1];
        gg[0] = t0.x; gg[1] = t0.y; gg[2] = t0.z; gg[3] = t0.w;
        gg[4] = t1.x; gg[5] = t1.y; gg[6] = t1.z; gg[7] = t1.w;
        t0 = *(const float4*)&lnb[n0]; t1 = *(const float4*)&lnb[n1];
        bb[0] = t0.x; bb[1] = t0.y; bb[2] = t0.z; bb[3] = t0.w;
        bb[4] = t1.x; bb[5] = t1.y; bb[6] = t1.z; bb[7] = t1.w;
    }
    const float inv128 = 1.0f / 128.0f;
    const float rsqrt2 = 0.70710678118654752f;

    #pragma unroll
    for (int mm = 0; mm < 8; mm++) {
        int pixg = m0 + ty * 8 + mm;
        float4 q0 = *(const float4*)&q[(size_t)pixg * CCH + n0];
        float4 q1 = *(const float4*)&q[(size_t)pixg * CCH + n1];
        float qv[8] = {q0.x, q0.y, q0.z, q0.w, q1.x, q1.y, q1.z, q1.w};
        float x[8];
        float s1 = 0.f, s2 = 0.f;
        #pragma unroll
        for (int n2 = 0; n2 < 4; n2++) {
            float lo, hi;
            upk2(acc[mm][n2], lo, hi);
            float p0 = lo + bi[n2 * 2 + 0];
            float p1 = hi + bi[n2 * 2 + 1];
            float e0 = 0.5f * p0 * (1.f + erff(p0 * rsqrt2));
            float e1 = 0.5f * p1 * (1.f + erff(p1 * rsqrt2));
            float x0 = e0 + qv[n2 * 2 + 0];
            float x1 = e1 + qv[n2 * 2 + 1];
            x[n2 * 2 + 0] = x0; x[n2 * 2 + 1] = x1;
            s1 += x0 + x1;
            s2 += x0 * x0 + x1 * x1;
        }
        // reduce across the 16 tx lanes (covers all 128 cols exactly once)
        #pragma unroll
        for (int ofs = 8; ofs >= 1; ofs >>= 1) {
            s1 += __shfl_xor_sync(0xffffffffu, s1, ofs);
            s2 += __shfl_xor_sync(0xffffffffu, s2, ofs);
        }
        float mean = s1 * inv128;
        float var = s2 * inv128 - mean * mean;
        float rstd = rsqrtf(var + 1e-5f);
        *(float4*)&out[(size_t)pixg * CCH + n0] = make_float4(
            (x[0] - mean) * rstd * gg[0] + bb[0],
            (x[1] - mean) * rstd * gg[1] + bb[1],
            (x[2] - mean) * rstd * gg[2] + bb[2],
            (x[3] - mean) * rstd * gg[3] + bb[3]);
        *(float4*)&out[(size_t)pixg * CCH + n1] = make_float4(
            (x[4] - mean) * rstd * gg[4] + bb[4],
            (x[5] - mean) * rstd * gg[5] + bb[5],
            (x[6] - mean) * rstd * gg[6] + bb[6],
            (x[7] - mean) * rstd * gg[7] + bb[7]);
    }
}

// ============================================================
extern "C" void kernel_launch(void* const* d_in, const int* in_sizes, int n_in,
                              void* d_out, int out_size) {
    const float* q    = (const float*)d_in[0];
    const float* kv   = (const float*)d_in[1];
    const float* pos  = (const float*)d_in[2];
    const float* W    = (const float*)d_in[3];
    const float* bias = (const float*)d_in[4];
    const float* lng  = (const float*)d_in[5];
    const float* lnb  = (const float*)d_in[6];
    float* out = (float*)d_out;

    static int smem_set = 0;
    if (!smem_set) {
        cudaFuncSetAttribute(score_kernel,
                             cudaFuncAttributeMaxDynamicSharedMemorySize, SMEM_SCORE);
        smem_set = 1;
    }

    prep_permute<<<62, 256>>>(W);
    prep_m2_partial<<<dim3(4, CCH), 128>>>(W, pos);
    prep_m2_combine<<<64, 256>>>();
    score_kernel<<<dim3(WW / 8, HH / 8, BATCH), 256, SMEM_SCORE>>>(q, kv);
    fused_gemm_kernel<<<NPIX / 64, 128>>>(q, bias, lng, lnb, out);
}